// round 16
// baseline (speedup 1.0000x reference)
#include <cuda_runtime.h>
#include <cuda_fp16.h>
#include <cstdint>

// TinyMoE: N=8192 tokens, H=1024, E=8, top-2.
// out[n,h] = sum_k w_k * (x[n] @ W_{e_k})[h] + sum_k w_k * p_k
//
// R16: R14 (147.6us) with the remap bias folded into the GEMM epilogue:
//  - out zeroed by cudaMemsetAsync (DMA) instead of prep prefill stores
//  - router stores gathered prob p per (token,slot); epilogue REDs
//    acc*wt + wt*p (exactly one bias add per output element per slot)

#define H      1024
#define NTOK   8192
#define NEXP   8
#define MAXPE  16384
#define BM     128
#define BN     128
#define BKH    64            // fp16 per k-slab (128 bytes)
#define KITER  (H / BKH)     // 16
#define PSTAGE 3

__device__ int    g_count[NEXP];
__device__ int    g_tok [NEXP][MAXPE];
__device__ float  g_wt  [NEXP][MAXPE];
__device__ float  g_pb  [NEXP][MAXPE];           // gathered router prob
__device__ __half g_xh[(size_t)NTOK * H];
__device__ __half g_wh[(size_t)NEXP * H * H];    // [e][out][in]

// ------------------------------------------------------------------ utils
__device__ __forceinline__ uint32_t smem_u32(const void* p) {
    uint32_t a;
    asm("{ .reg .u64 t; cvta.to.shared.u64 t, %1; cvt.u32.u64 %0, t; }"
        : "=r"(a) : "l"(p));
    return a;
}
#define SWZ(o) ((o) ^ ((((uint32_t)(o)) >> 3) & 0x70))

__device__ __forceinline__ void cp16(uint32_t d, const void* s) {
    asm volatile("cp.async.cg.shared.global [%0], [%1], 16;" :: "r"(d), "l"(s));
}
#define CP_COMMIT()  asm volatile("cp.async.commit_group;" ::: "memory")
#define CP_WAIT1()   asm volatile("cp.async.wait_group 1;" ::: "memory")
#define CP_WAIT0()   asm volatile("cp.async.wait_group 0;" ::: "memory")

__device__ __forceinline__ void ldm4(uint32_t a, uint32_t& r0, uint32_t& r1,
                                     uint32_t& r2, uint32_t& r3) {
    asm volatile("ldmatrix.sync.aligned.m8n8.x4.shared.b16 {%0,%1,%2,%3}, [%4];"
                 : "=r"(r0), "=r"(r1), "=r"(r2), "=r"(r3) : "r"(a));
}
__device__ __forceinline__ void mma16816(float* c, const uint32_t* a,
                                         uint32_t b0, uint32_t b1) {
    asm volatile(
        "mma.sync.aligned.m16n8k16.row.col.f32.f16.f16.f32 "
        "{%0,%1,%2,%3}, {%4,%5,%6,%7}, {%8,%9}, {%0,%1,%2,%3};"
        : "+f"(c[0]), "+f"(c[1]), "+f"(c[2]), "+f"(c[3])
        : "r"(a[0]), "r"(a[1]), "r"(a[2]), "r"(a[3]), "r"(b0), "r"(b1));
}
__device__ __forceinline__ void red_add_v2(float* p, float a, float b) {
    asm volatile("red.global.add.v2.f32 [%0], {%1, %2};"
                 :: "l"(p), "f"(a), "f"(b) : "memory");
}

// ------------------------------------------------------------------ fused prep
// blocks [0, 2048): convert+transpose W[e][in][out] fp32 -> g_wh[e][out][in]
// blocks [2048, 3072): router (logits/softmax/top2/bucket) + x -> fp16
union PrepShared {
    float tile[64][65];          // 16.9 KB (convert_w)
    float rwbuf[NEXP * H];       // 32 KB   (router)
};

__global__ __launch_bounds__(256) void prep_kernel(const float* __restrict__ W,
                                                   const float* __restrict__ x,
                                                   const float* __restrict__ rw) {
    __shared__ __align__(16) PrepShared sm;
    int t = threadIdx.x;

    if (blockIdx.x < 2048) {
        // ---------------- convert_w: 64x64 tile, 256 blocks per expert (16x16)
        int b  = blockIdx.x;
        int e  = b >> 8;
        int h0 = ((b >> 4) & 15) * 64;
        int o0 = (b & 15) * 64;
        int row = t >> 4, c4 = (t & 15) * 4;
        const float* src = W + ((size_t)e * H + h0) * H + o0;
        #pragma unroll
        for (int i = 0; i < 4; i++) {
            float4 v = *(const float4*)(src + (size_t)(row + i * 16) * H + c4);
            sm.tile[row + i * 16][c4 + 0] = v.x;
            sm.tile[row + i * 16][c4 + 1] = v.y;
            sm.tile[row + i * 16][c4 + 2] = v.z;
            sm.tile[row + i * 16][c4 + 3] = v.w;
        }
        __syncthreads();
        int orow = t >> 5, ip = (t & 31) * 2;
        #pragma unroll
        for (int i = 0; i < 8; i++) {
            int r = orow + i * 8;
            __half2 hv = __floats2half2_rn(sm.tile[ip][r], sm.tile[ip + 1][r]);
            *(__half2*)(g_wh + ((size_t)e * H + o0 + r) * H + h0 + ip) = hv;
        }
    } else {
        // ---------------- router + convert_x: one warp per token
        {
            const float4* rwg = (const float4*)rw;
            float4* s4 = (float4*)sm.rwbuf;
            #pragma unroll
            for (int i = 0; i < (NEXP * H / 4) / 256; i++)
                s4[t + i * 256] = rwg[t + i * 256];
        }
        __syncthreads();

        int wid = t >> 5, lane = t & 31;
        int n = (blockIdx.x - 2048) * 8 + wid;
        const float4* xr = (const float4*)(x + (size_t)n * H);
        __half2* xo = (__half2*)(g_xh + (size_t)n * H);
        const float4* rw4 = (const float4*)sm.rwbuf;

        float acc[NEXP];
        #pragma unroll
        for (int e = 0; e < NEXP; e++) acc[e] = 0.f;
        #pragma unroll
        for (int i = 0; i < 8; i++) {
            float4 xv = xr[i * 32 + lane];
            xo[(i * 32 + lane) * 2 + 0] = __floats2half2_rn(xv.x, xv.y);
            xo[(i * 32 + lane) * 2 + 1] = __floats2half2_rn(xv.z, xv.w);
            #pragma unroll
            for (int e = 0; e < NEXP; e++) {
                float4 rv = rw4[e * 256 + i * 32 + lane];
                acc[e] += xv.x * rv.x + xv.y * rv.y + xv.z * rv.z + xv.w * rv.w;
            }
        }
        #pragma unroll
        for (int e = 0; e < NEXP; e++) {
            #pragma unroll
            for (int off = 16; off > 0; off >>= 1)
                acc[e] += __shfl_xor_sync(0xffffffffu, acc[e], off);
        }
        if (lane == 0) {
            float m = acc[0];
            #pragma unroll
            for (int e = 1; e < NEXP; e++) m = fmaxf(m, acc[e]);
            float p[NEXP]; float s = 0.f;
            #pragma unroll
            for (int e = 0; e < NEXP; e++) { p[e] = expf(acc[e] - m); s += p[e]; }
            float inv = 1.f / s;
            int b1 = 0; float v1 = acc[0];
            #pragma unroll
            for (int e = 1; e < NEXP; e++) if (acc[e] > v1) { v1 = acc[e]; b1 = e; }
            int b2 = -1; float v2 = -3.4e38f;
            #pragma unroll
            for (int e = 0; e < NEXP; e++)
                if (e != b1 && acc[e] > v2) { v2 = acc[e]; b2 = e; }
            float p0 = p[b1] * inv, p1 = p[b2] * inv;
            float ws = 1.f / (p0 + p1 + 1e-6f);
            float w0 = p0 * ws, w1 = p1 * ws;
            int pos0 = atomicAdd(&g_count[b1], 1);
            g_tok[b1][pos0] = n; g_wt[b1][pos0] = w0; g_pb[b1][pos0] = p0;
            int pos1 = atomicAdd(&g_count[b2], 1);
            g_tok[b2][pos1] = n; g_wt[b2][pos1] = w1; g_pb[b2][pos1] = p1;
        }
    }
}

// ------------------------------------------------------------------ HMMA GEMM
// 128x128 tile, K=1024, 3-stage cp.async pipeline, 8 warps (2x4), warp 64x32.
// Epilogue: red.v2 of (acc*wt + wt*p) into zero-initialized out.
#define STAGE_BYTES 32768                       // A 16KB + B 16KB
#define SMEM_BYTES  (PSTAGE * STAGE_BYTES)      // 96 KB -> 2 CTAs/SM

__global__ __launch_bounds__(256, 2) void expert_gemm(float* __restrict__ out) {
    extern __shared__ char smem[];
    __shared__ int   s_tok[BM];
    __shared__ float s_wt [BM];
    __shared__ float s_bias[BM];

    int e = blockIdx.z;
    int cnt = g_count[e];
    int m0 = blockIdx.x * BM;
    if (m0 >= cnt) return;
    int n0 = blockIdx.y * BN;

    int t = threadIdx.x;
    if (t < BM) {
        int src = min(m0 + t, cnt - 1);
        float wt = g_wt[e][src];
        s_tok[t]  = g_tok[e][src];
        s_wt[t]   = wt;
        s_bias[t] = wt * g_pb[e][src];
    }
    __syncthreads();

    const uint32_t sb = smem_u32(smem);

    // ---- loader: thread t covers rows lr+32*i (i<4), 16B chunk lc
    const int lr = t >> 3, lc = t & 7;
    const __half* aptr[4];
    const __half* bptr[4];
    #pragma unroll
    for (int i = 0; i < 4; i++) {
        int r = lr + 32 * i;
        aptr[i] = g_xh + (size_t)s_tok[r] * H + lc * 8;
        bptr[i] = g_wh + ((size_t)e * H + n0 + r) * H + lc * 8;
    }
    const uint32_t dsw = SWZ(lr * 128 + lc * 16);

    #define ISSUE(it) do {                                                   \
        int _st = (it) % PSTAGE; int _k0 = (it) * BKH;                       \
        uint32_t _ab = sb + _st * STAGE_BYTES;                               \
        uint32_t _bb = _ab + 16384;                                          \
        _Pragma("unroll")                                                    \
        for (int _i = 0; _i < 4; _i++) {                                     \
            cp16(_ab + (dsw + _i * 4096), aptr[_i] + _k0);                   \
            cp16(_bb + (dsw + _i * 4096), bptr[_i] + _k0);                   \
        }                                                                    \
    } while (0)

    ISSUE(0); CP_COMMIT();
    ISSUE(1); CP_COMMIT();

    // ---- compute setup: 8 warps as 2(M) x 4(N), warp tile 64x32
    int lane = t & 31, wid = t >> 5;
    int wm = wid & 1, wn = wid >> 1;
    int arow0 = wm * 64 + (lane & 15);
    int brow0 = wn * 32 + (lane & 15);
    int csel  = (lane >> 4) * 16;

    float acc[4][4][4];
    #pragma unroll
    for (int a = 0; a < 4; a++)
        #pragma unroll
        for (int b = 0; b < 4; b++)
            #pragma unroll
            for (int c = 0; c < 4; c++) acc[a][b][c] = 0.f;

    for (int it = 0; it < KITER; it++) {
        if (it + 2 < KITER) {
            CP_WAIT1();
            __syncthreads();
            ISSUE(it + 2);
            CP_COMMIT();
        } else if (it + 2 == KITER) {
            CP_WAIT1();
            __syncthreads();
        } else {
            CP_WAIT0();
            __syncthreads();
        }

        uint32_t ab = sb + (it % PSTAGE) * STAGE_BYTES;
        uint32_t bb = ab + 16384;
        #pragma unroll
        for (int kk = 0; kk < 4; kk++) {
            int colb = kk * 32 + csel;
            uint32_t afr[4][4];
            #pragma unroll
            for (int im = 0; im < 4; im++)
                ldm4(ab + SWZ((arow0 + im * 16) * 128 + colb),
                     afr[im][0], afr[im][1], afr[im][2], afr[im][3]);
            uint32_t bfr[2][4];
            #pragma unroll
            for (int j = 0; j < 2; j++)
                ldm4(bb + SWZ((brow0 + j * 16) * 128 + colb),
                     bfr[j][0], bfr[j][1], bfr[j][2], bfr[j][3]);
            #pragma unroll
            for (int im = 0; im < 4; im++) {
                mma16816(acc[im][0], afr[im], bfr[0][0], bfr[0][2]);
                mma16816(acc[im][1], afr[im], bfr[0][1], bfr[0][3]);
                mma16816(acc[im][2], afr[im], bfr[1][0], bfr[1][2]);
                mma16816(acc[im][3], afr[im], bfr[1][1], bfr[1][3]);
            }
        }
    }
    #undef ISSUE

    // ---- epilogue: red.v2 of (acc*wt + bias) into zeroed out
    int qr = lane >> 2, qc = (lane & 3) * 2;
    #pragma unroll
    for (int im = 0; im < 4; im++) {
        #pragma unroll
        for (int p = 0; p < 2; p++) {
            int r = wm * 64 + im * 16 + p * 8 + qr;
            if (m0 + r < cnt) {
                float wt = s_wt[r];
                float bs = s_bias[r];
                float* dst = out + (size_t)s_tok[r] * H + n0 + wn * 32 + qc;
                #pragma unroll
                for (int inn = 0; inn < 4; inn++) {
                    red_add_v2(dst + inn * 8,
                               fmaf(acc[im][inn][p * 2 + 0], wt, bs),
                               fmaf(acc[im][inn][p * 2 + 1], wt, bs));
                }
            }
        }
    }
}

// ------------------------------------------------------------------ launch
extern "C" void kernel_launch(void* const* d_in, const int* in_sizes, int n_in,
                              void* d_out, int out_size) {
    const float* x  = (const float*)d_in[0];   // [8192, 1024]
    const float* rw = (const float*)d_in[1];   // [8, 1024]
    const float* W  = (const float*)d_in[2];   // [8, 1024, 1024]
    float* out = (float*)d_out;

    cudaFuncSetAttribute(expert_gemm, cudaFuncAttributeMaxDynamicSharedMemorySize,
                         SMEM_BYTES);

    void* cnt_ptr = nullptr;
    cudaGetSymbolAddress(&cnt_ptr, g_count);
    cudaMemsetAsync(cnt_ptr, 0, NEXP * sizeof(int));
    cudaMemsetAsync(out, 0, (size_t)NTOK * H * sizeof(float));

    prep_kernel<<<3072, 256>>>(W, x, rw);
    expert_gemm<<<dim3(MAXPE / BM, H / BN, NEXP), 256, SMEM_BYTES>>>(out);
}

// round 17
// speedup vs baseline: 1.0502x; 1.0502x over previous
#include <cuda_runtime.h>
#include <cuda_fp16.h>
#include <cstdint>

// TinyMoE: N=8192 tokens, H=1024, E=8, top-2.
// out[n,h] = sum_k w_k * (x[n] @ W_{e_k})[h] + C_n
//
// R17: R14 (best: 147.6us) +
//  - W-transpose path slimmed: tile[64][68], STS.128 fill, STG.128 store
//    (saves ~18 issue slots/thread in 2048 prep blocks)
//  - gemm grid.x 128 -> 32 with worst-case-safe m-tile stride loop
//  - dead g_slot removed

#define H      1024
#define NTOK   8192
#define NEXP   8
#define MAXPE  16384
#define BM     128
#define BN     128
#define BKH    64            // fp16 per k-slab (128 bytes)
#define KITER  (H / BKH)     // 16
#define PSTAGE 3
#define MTILES 32            // gemm grid.x; stride loop covers overflow

__device__ int    g_count[NEXP];
__device__ int    g_tok [NEXP][MAXPE];
__device__ float  g_wt  [NEXP][MAXPE];
__device__ __half g_xh[(size_t)NTOK * H];
__device__ __half g_wh[(size_t)NEXP * H * H];    // [e][out][in]

// ------------------------------------------------------------------ utils
__device__ __forceinline__ uint32_t smem_u32(const void* p) {
    uint32_t a;
    asm("{ .reg .u64 t; cvta.to.shared.u64 t, %1; cvt.u32.u64 %0, t; }"
        : "=r"(a) : "l"(p));
    return a;
}
#define SWZ(o) ((o) ^ ((((uint32_t)(o)) >> 3) & 0x70))

__device__ __forceinline__ void cp16(uint32_t d, const void* s) {
    asm volatile("cp.async.cg.shared.global [%0], [%1], 16;" :: "r"(d), "l"(s));
}
#define CP_COMMIT()  asm volatile("cp.async.commit_group;" ::: "memory")
#define CP_WAIT1()   asm volatile("cp.async.wait_group 1;" ::: "memory")
#define CP_WAIT0()   asm volatile("cp.async.wait_group 0;" ::: "memory")

__device__ __forceinline__ void ldm4(uint32_t a, uint32_t& r0, uint32_t& r1,
                                     uint32_t& r2, uint32_t& r3) {
    asm volatile("ldmatrix.sync.aligned.m8n8.x4.shared.b16 {%0,%1,%2,%3}, [%4];"
                 : "=r"(r0), "=r"(r1), "=r"(r2), "=r"(r3) : "r"(a));
}
__device__ __forceinline__ void mma16816(float* c, const uint32_t* a,
                                         uint32_t b0, uint32_t b1) {
    asm volatile(
        "mma.sync.aligned.m16n8k16.row.col.f32.f16.f16.f32 "
        "{%0,%1,%2,%3}, {%4,%5,%6,%7}, {%8,%9}, {%0,%1,%2,%3};"
        : "+f"(c[0]), "+f"(c[1]), "+f"(c[2]), "+f"(c[3])
        : "r"(a[0]), "r"(a[1]), "r"(a[2]), "r"(a[3]), "r"(b0), "r"(b1));
}
__device__ __forceinline__ void red_add_v2(float* p, float a, float b) {
    asm volatile("red.global.add.v2.f32 [%0], {%1, %2};"
                 :: "l"(p), "f"(a), "f"(b) : "memory");
}

// ------------------------------------------------------------------ fused prep
// blocks [0, 2048): convert+transpose W[e][in][out] fp32 -> g_wh[e][out][in]
// blocks [2048, 3072): router + x -> fp16 + prefill out with C_n
union PrepShared {
    float tile[64][68];          // 17.4 KB (convert_w; 68 keeps 16B row align)
    float rwbuf[NEXP * H];       // 32 KB   (router)
};

__global__ __launch_bounds__(256) void prep_kernel(const float* __restrict__ W,
                                                   const float* __restrict__ x,
                                                   const float* __restrict__ rw,
                                                   float* __restrict__ out) {
    __shared__ __align__(16) PrepShared sm;
    int t = threadIdx.x;

    if (blockIdx.x < 2048) {
        // ---------------- convert_w: 64x64 tile, 256 blocks per expert (16x16)
        int b  = blockIdx.x;
        int e  = b >> 8;
        int h0 = ((b >> 4) & 15) * 64;
        int o0 = (b & 15) * 64;
        // fill: thread t loads rows row+16i, 4-float chunk c4 (STS.128)
        int row = t >> 4, c4 = (t & 15) * 4;
        const float* src = W + ((size_t)e * H + h0) * H + o0;
        #pragma unroll
        for (int i = 0; i < 4; i++) {
            float4 v = *(const float4*)(src + (size_t)(row + i * 16) * H + c4);
            *(float4*)&sm.tile[row + i * 16][c4] = v;
        }
        __syncthreads();
        // store: thread t owns output row r = t>>2, half-segment cseg = (t&3)*16
        // produces 16 contiguous halves -> 2 STG.128
        int r = t >> 2, cseg = (t & 3) * 16;
        uint32_t hv[8];
        #pragma unroll
        for (int j = 0; j < 8; j++) {
            __half2 h2 = __floats2half2_rn(sm.tile[cseg + 2 * j][r],
                                           sm.tile[cseg + 2 * j + 1][r]);
            hv[j] = *(uint32_t*)&h2;
        }
        __half* dst = g_wh + ((size_t)e * H + o0 + r) * H + h0 + cseg;
        ((uint4*)dst)[0] = make_uint4(hv[0], hv[1], hv[2], hv[3]);
        ((uint4*)dst)[1] = make_uint4(hv[4], hv[5], hv[6], hv[7]);
    } else {
        // ---------------- router + convert_x + out prefill: one warp per token
        {
            const float4* rwg = (const float4*)rw;
            float4* s4 = (float4*)sm.rwbuf;
            #pragma unroll
            for (int i = 0; i < (NEXP * H / 4) / 256; i++)
                s4[t + i * 256] = rwg[t + i * 256];
        }
        __syncthreads();

        int wid = t >> 5, lane = t & 31;
        int n = (blockIdx.x - 2048) * 8 + wid;
        const float4* xr = (const float4*)(x + (size_t)n * H);
        __half2* xo = (__half2*)(g_xh + (size_t)n * H);
        const float4* rw4 = (const float4*)sm.rwbuf;

        float acc[NEXP];
        #pragma unroll
        for (int e = 0; e < NEXP; e++) acc[e] = 0.f;
        #pragma unroll
        for (int i = 0; i < 8; i++) {
            float4 xv = xr[i * 32 + lane];
            xo[(i * 32 + lane) * 2 + 0] = __floats2half2_rn(xv.x, xv.y);
            xo[(i * 32 + lane) * 2 + 1] = __floats2half2_rn(xv.z, xv.w);
            #pragma unroll
            for (int e = 0; e < NEXP; e++) {
                float4 rv = rw4[e * 256 + i * 32 + lane];
                acc[e] += xv.x * rv.x + xv.y * rv.y + xv.z * rv.z + xv.w * rv.w;
            }
        }
        #pragma unroll
        for (int e = 0; e < NEXP; e++) {
            #pragma unroll
            for (int off = 16; off > 0; off >>= 1)
                acc[e] += __shfl_xor_sync(0xffffffffu, acc[e], off);
        }
        float Cn = 0.f;
        if (lane == 0) {
            float m = acc[0];
            #pragma unroll
            for (int e = 1; e < NEXP; e++) m = fmaxf(m, acc[e]);
            float p[NEXP]; float s = 0.f;
            #pragma unroll
            for (int e = 0; e < NEXP; e++) { p[e] = expf(acc[e] - m); s += p[e]; }
            float inv = 1.f / s;
            int b1 = 0; float v1 = acc[0];
            #pragma unroll
            for (int e = 1; e < NEXP; e++) if (acc[e] > v1) { v1 = acc[e]; b1 = e; }
            int b2 = -1; float v2 = -3.4e38f;
            #pragma unroll
            for (int e = 0; e < NEXP; e++)
                if (e != b1 && acc[e] > v2) { v2 = acc[e]; b2 = e; }
            float p0 = p[b1] * inv, p1 = p[b2] * inv;
            float ws = 1.f / (p0 + p1 + 1e-6f);
            float w0 = p0 * ws, w1 = p1 * ws;
            Cn = w0 * p0 + w1 * p1;
            int pos0 = atomicAdd(&g_count[b1], 1);
            g_tok[b1][pos0] = n; g_wt[b1][pos0] = w0;
            int pos1 = atomicAdd(&g_count[b2], 1);
            g_tok[b2][pos1] = n; g_wt[b2][pos1] = w1;
        }
        // broadcast C_n and prefill the output row
        Cn = __shfl_sync(0xffffffffu, Cn, 0);
        float4 cv = make_float4(Cn, Cn, Cn, Cn);
        float4* orow = (float4*)(out + (size_t)n * H);
        #pragma unroll
        for (int i = 0; i < 8; i++)
            orow[i * 32 + lane] = cv;
    }
}

// ------------------------------------------------------------------ HMMA GEMM
// 128x128 tile, K=1024, 3-stage cp.async pipeline, 8 warps (2x4), warp 64x32.
// grid.x = 32; m-tile stride loop covers any routing skew.
// Epilogue: red.global.add.v2.f32 weighted fp32 pairs into C_n-prefilled out.
#define STAGE_BYTES 32768                       // A 16KB + B 16KB
#define SMEM_BYTES  (PSTAGE * STAGE_BYTES)      // 96 KB -> 2 CTAs/SM

__global__ __launch_bounds__(256, 2) void expert_gemm(float* __restrict__ out) {
    extern __shared__ char smem[];
    __shared__ int   s_tok[BM];
    __shared__ float s_wt [BM];

    int e = blockIdx.z;
    int cnt = g_count[e];
    int n0 = blockIdx.y * BN;

    int t = threadIdx.x;
    const uint32_t sb = smem_u32(smem);
    const int lr = t >> 3, lc = t & 7;
    const uint32_t dsw = SWZ(lr * 128 + lc * 16);
    int lane = t & 31, wid = t >> 5;
    int wm = wid & 1, wn = wid >> 1;
    int arow0 = wm * 64 + (lane & 15);
    int brow0 = wn * 32 + (lane & 15);
    int csel  = (lane >> 4) * 16;
    int qr = lane >> 2, qc = (lane & 3) * 2;

    for (int mt = blockIdx.x; mt * BM < cnt; mt += MTILES) {
        int m0 = mt * BM;
        __syncthreads();                      // protect s_tok/s_wt reuse
        if (t < BM) {
            int src = min(m0 + t, cnt - 1);
            s_tok[t] = g_tok[e][src];
            s_wt[t]  = g_wt[e][src];
        }
        __syncthreads();

        const __half* aptr[4];
        const __half* bptr[4];
        #pragma unroll
        for (int i = 0; i < 4; i++) {
            int r = lr + 32 * i;
            aptr[i] = g_xh + (size_t)s_tok[r] * H + lc * 8;
            bptr[i] = g_wh + ((size_t)e * H + n0 + r) * H + lc * 8;
        }

        #define ISSUE(it) do {                                               \
            int _st = (it) % PSTAGE; int _k0 = (it) * BKH;                   \
            uint32_t _ab = sb + _st * STAGE_BYTES;                           \
            uint32_t _bb = _ab + 16384;                                      \
            _Pragma("unroll")                                                \
            for (int _i = 0; _i < 4; _i++) {                                 \
                cp16(_ab + (dsw + _i * 4096), aptr[_i] + _k0);               \
                cp16(_bb + (dsw + _i * 4096), bptr[_i] + _k0);               \
            }                                                                \
        } while (0)

        ISSUE(0); CP_COMMIT();
        ISSUE(1); CP_COMMIT();

        float acc[4][4][4];
        #pragma unroll
        for (int a = 0; a < 4; a++)
            #pragma unroll
            for (int b = 0; b < 4; b++)
                #pragma unroll
                for (int c = 0; c < 4; c++) acc[a][b][c] = 0.f;

        for (int it = 0; it < KITER; it++) {
            if (it + 2 < KITER) {
                CP_WAIT1();
                __syncthreads();
                ISSUE(it + 2);
                CP_COMMIT();
            } else if (it + 2 == KITER) {
                CP_WAIT1();
                __syncthreads();
            } else {
                CP_WAIT0();
                __syncthreads();
            }

            uint32_t ab = sb + (it % PSTAGE) * STAGE_BYTES;
            uint32_t bb = ab + 16384;
            #pragma unroll
            for (int kk = 0; kk < 4; kk++) {
                int colb = kk * 32 + csel;
                uint32_t afr[4][4];
                #pragma unroll
                for (int im = 0; im < 4; im++)
                    ldm4(ab + SWZ((arow0 + im * 16) * 128 + colb),
                         afr[im][0], afr[im][1], afr[im][2], afr[im][3]);
                uint32_t bfr[2][4];
                #pragma unroll
                for (int j = 0; j < 2; j++)
                    ldm4(bb + SWZ((brow0 + j * 16) * 128 + colb),
                         bfr[j][0], bfr[j][1], bfr[j][2], bfr[j][3]);
                #pragma unroll
                for (int im = 0; im < 4; im++) {
                    mma16816(acc[im][0], afr[im], bfr[0][0], bfr[0][2]);
                    mma16816(acc[im][1], afr[im], bfr[0][1], bfr[0][3]);
                    mma16816(acc[im][2], afr[im], bfr[1][0], bfr[1][2]);
                    mma16816(acc[im][3], afr[im], bfr[1][1], bfr[1][3]);
                }
            }
        }
        #undef ISSUE

        // ---- epilogue: vectorized reductions of weighted fp32 pairs into out
        #pragma unroll
        for (int im = 0; im < 4; im++) {
            #pragma unroll
            for (int p = 0; p < 2; p++) {
                int r = wm * 64 + im * 16 + p * 8 + qr;
                if (m0 + r < cnt) {
                    float wt = s_wt[r];
                    float* dst = out + (size_t)s_tok[r] * H + n0 + wn * 32 + qc;
                    #pragma unroll
                    for (int inn = 0; inn < 4; inn++) {
                        red_add_v2(dst + inn * 8,
                                   acc[im][inn][p * 2 + 0] * wt,
                                   acc[im][inn][p * 2 + 1] * wt);
                    }
                }
            }
        }
    }
}

// ------------------------------------------------------------------ launch
extern "C" void kernel_launch(void* const* d_in, const int* in_sizes, int n_in,
                              void* d_out, int out_size) {
    const float* x  = (const float*)d_in[0];   // [8192, 1024]
    const float* rw = (const float*)d_in[1];   // [8, 1024]
    const float* W  = (const float*)d_in[2];   // [8, 1024, 1024]
    float* out = (float*)d_out;

    cudaFuncSetAttribute(expert_gemm, cudaFuncAttributeMaxDynamicSharedMemorySize,
                         SMEM_BYTES);

    void* cnt_ptr = nullptr;
    cudaGetSymbolAddress(&cnt_ptr, g_count);
    cudaMemsetAsync(cnt_ptr, 0, NEXP * sizeof(int));

    prep_kernel<<<3072, 256>>>(W, x, rw, out);
    expert_gemm<<<dim3(MTILES, H / BN, NEXP), 256, SMEM_BYTES>>>(out);
}